// round 2
// baseline (speedup 1.0000x reference)
#include <cuda_runtime.h>
#include <stdint.h>

// Problem constants
#define B     1024
#define S     2048
#define R1    20000
#define R2    40000

#define MAIN_THREADS 512

// ---------------- static device scratch (no runtime allocation) ----------------
__device__ int       g_counts1[S];
__device__ int       g_counts2[S];
__device__ int       g_cur1[S];
__device__ int       g_cur2[S];
// Packed entries, grouped by product species (key):
//   e1 = ra | key<<11 | rid<<22          (11 + 11 + 15 bits)
//   e2 = ra | rb<<11 | key<<22 | rid<<33 (11 + 11 + 11 + 16 bits)
__device__ uint64_t  g_e1[R1];
__device__ uint64_t  g_e2[R2];

// ---------------- prep kernels ----------------

__global__ void init_counts_kernel() {
    int i = blockIdx.x * blockDim.x + threadIdx.x;
    if (i < S) { g_counts1[i] = 0; g_counts2[i] = 0; }
}

__global__ void hist_kernel(const int* __restrict__ inds_1p,
                            const int* __restrict__ inds_2p) {
    int i = blockIdx.x * blockDim.x + threadIdx.x;
    if (i < R1) {
        atomicAdd(&g_counts1[inds_1p[i]], 1);
    } else if (i < R1 + R2) {
        atomicAdd(&g_counts2[inds_2p[i - R1]], 1);
    }
}

// Single-CTA exclusive scan over 2048 bins (twice), writing running cursors.
__global__ void scan_kernel() {
    __shared__ int buf[2][S];
    const int tid = threadIdx.x;   // 1024 threads, 2 elems each

    for (int pass = 0; pass < 2; ++pass) {
        const int* cnt = pass == 0 ? g_counts1 : g_counts2;
        int*       cur = pass == 0 ? g_cur1    : g_cur2;

        buf[0][tid]        = cnt[tid];
        buf[0][tid + 1024] = cnt[tid + 1024];
        __syncthreads();

        int src = 0;
        for (int off = 1; off < S; off <<= 1) {
            int i0 = tid, i1 = tid + 1024;
            int v0 = buf[src][i0] + (i0 >= off ? buf[src][i0 - off] : 0);
            int v1 = buf[src][i1] + (i1 >= off ? buf[src][i1 - off] : 0);
            __syncthreads();
            buf[1 - src][i0] = v0;
            buf[1 - src][i1] = v1;
            __syncthreads();
            src ^= 1;
        }
        cur[tid]        = (tid == 0) ? 0 : buf[src][tid - 1];
        cur[tid + 1024] = buf[src][tid + 1023];
        __syncthreads();
    }
}

__global__ void scatter_kernel(const int* __restrict__ inds_1r,
                               const int* __restrict__ inds_1p,
                               const int* __restrict__ inds_2r,
                               const int* __restrict__ inds_2p) {
    int i = blockIdx.x * blockDim.x + threadIdx.x;
    if (i < R1) {
        int p = inds_1p[i];
        int pos = atomicAdd(&g_cur1[p], 1);
        g_e1[pos] = (uint64_t)(uint32_t)inds_1r[i]
                  | ((uint64_t)(uint32_t)p   << 11)
                  | ((uint64_t)(uint32_t)i   << 22);
    } else if (i < R1 + R2) {
        int j = i - R1;
        int p = inds_2p[j];
        int pos = atomicAdd(&g_cur2[p], 1);
        g_e2[pos] = (uint64_t)(uint32_t)inds_2r[2 * j]
                  | ((uint64_t)(uint32_t)inds_2r[2 * j + 1] << 11)
                  | ((uint64_t)(uint32_t)p                  << 22)
                  | ((uint64_t)(uint32_t)j                  << 33);
    }
}

// ---------------- main kernel ----------------
// One CTA per batch row. Entries processed coalesced in key-grouped order;
// warp-segmented reduction collapses each product segment to one SMEM atomic.
//
// SMEM: y row (2048) + accumulator (2048) + rate buffer (40000) = 176,384 B.

#define SMEM_FLOATS (S + S + R2)

__global__ __launch_bounds__(MAIN_THREADS, 1)
void reaction_main_kernel(const float* __restrict__ y_in,
                          const float* __restrict__ rates_1st,
                          const float* __restrict__ rates_2nd,
                          float* __restrict__ y_out) {
    extern __shared__ float sm[];
    float* y_s   = sm;            // [S]
    float* acc_s = sm + S;        // [S]
    float* rbuf  = sm + 2 * S;    // [R2]

    const int b    = blockIdx.x;
    const int tid  = threadIdx.x;
    const int lane = tid & 31;

    // Load y row + zero the accumulator (one float4 each)
    {
        const float4* src = (const float4*)(y_in + (size_t)b * S);
        ((float4*)y_s)[tid]   = src[tid];
        ((float4*)acc_s)[tid] = make_float4(0.f, 0.f, 0.f, 0.f);
    }

    // ---- Phase A: stage rates_1st (coalesced float4) ----
    {
        const float4* src = (const float4*)(rates_1st + (size_t)b * R1);
        #pragma unroll
        for (int i = tid; i < R1 / 4; i += MAIN_THREADS)
            ((float4*)rbuf)[i] = src[i];
    }
    __syncthreads();

    // ---- Phase A: coalesced entry sweep + segmented reduce ----
    for (int i = tid; i < ((R1 + MAIN_THREADS - 1) / MAIN_THREADS) * MAIN_THREADS;
         i += MAIN_THREADS) {
        const bool valid = (i < R1);
        unsigned k = 0xFFFFu;
        float    v = 0.f;
        if (valid) {
            uint64_t e  = g_e1[i];
            unsigned ra = (unsigned)e & 2047u;
            k           = ((unsigned)(e >> 11)) & 2047u;
            unsigned rid = (unsigned)(e >> 22);
            v = y_s[ra] * rbuf[rid];
        }
        // head flags -> segment-start index per lane
        unsigned pk = __shfl_up_sync(0xffffffffu, k, 1);
        bool head = (lane == 0) || (pk != k);
        unsigned hd = __ballot_sync(0xffffffffu, head);
        unsigned lmask = (lane == 31) ? 0xffffffffu : ((1u << (lane + 1)) - 1u);
        int s = 31 - __clz(hd & lmask);
        #pragma unroll
        for (int d = 1; d < 32; d <<= 1) {
            float pv = __shfl_up_sync(0xffffffffu, v, d);
            if (lane - d >= s) v += pv;
        }
        bool tail = (lane == 31) || ((hd >> (lane + 1)) & 1u);
        if (tail && valid) atomicAdd(&acc_s[k], v);
    }
    __syncthreads();   // phase-A rbuf reads done before overwrite

    // ---- Phase B: stage rates_2nd ----
    {
        const float4* src = (const float4*)(rates_2nd + (size_t)b * R2);
        #pragma unroll
        for (int i = tid; i < R2 / 4; i += MAIN_THREADS)
            ((float4*)rbuf)[i] = src[i];
    }
    __syncthreads();

    // ---- Phase B: coalesced entry sweep + segmented reduce ----
    for (int i = tid; i < ((R2 + MAIN_THREADS - 1) / MAIN_THREADS) * MAIN_THREADS;
         i += MAIN_THREADS) {
        const bool valid = (i < R2);
        unsigned k = 0xFFFFu;
        float    v = 0.f;
        if (valid) {
            uint64_t e  = g_e2[i];
            unsigned ra = (unsigned)e & 2047u;
            unsigned rb = ((unsigned)(e >> 11)) & 2047u;
            k           = ((unsigned)(e >> 22)) & 2047u;
            unsigned rid = (unsigned)(e >> 33);
            v = y_s[ra] * y_s[rb] * rbuf[rid];
        }
        unsigned pk = __shfl_up_sync(0xffffffffu, k, 1);
        bool head = (lane == 0) || (pk != k);
        unsigned hd = __ballot_sync(0xffffffffu, head);
        unsigned lmask = (lane == 31) ? 0xffffffffu : ((1u << (lane + 1)) - 1u);
        int s = 31 - __clz(hd & lmask);
        #pragma unroll
        for (int d = 1; d < 32; d <<= 1) {
            float pv = __shfl_up_sync(0xffffffffu, v, d);
            if (lane - d >= s) v += pv;
        }
        bool tail = (lane == 31) || ((hd >> (lane + 1)) & 1u);
        if (tail && valid) atomicAdd(&acc_s[k], v);
    }
    __syncthreads();

    // ---- write out (coalesced float4) ----
    ((float4*)(y_out + (size_t)b * S))[tid] = ((const float4*)acc_s)[tid];
}

// ---------------- launch ----------------

extern "C" void kernel_launch(void* const* d_in, const int* in_sizes, int n_in,
                              void* d_out, int out_size) {
    const float* y_in      = (const float*)d_in[0];
    const float* rates_1st = (const float*)d_in[1];
    const float* rates_2nd = (const float*)d_in[2];
    const int*   inds_1r   = (const int*)d_in[3];
    const int*   inds_1p   = (const int*)d_in[4];
    const int*   inds_2r   = (const int*)d_in[5];
    const int*   inds_2p   = (const int*)d_in[6];
    float*       y_out     = (float*)d_out;

    cudaFuncSetAttribute(reaction_main_kernel,
                         cudaFuncAttributeMaxDynamicSharedMemorySize,
                         SMEM_FLOATS * (int)sizeof(float));

    // CSR build (rebuilt every launch; deterministic)
    init_counts_kernel<<<(S + 255) / 256, 256>>>();
    hist_kernel<<<(R1 + R2 + 255) / 256, 256>>>(inds_1p, inds_2p);
    scan_kernel<<<1, 1024>>>();
    scatter_kernel<<<(R1 + R2 + 255) / 256, 256>>>(inds_1r, inds_1p, inds_2r, inds_2p);

    // Main pass: one CTA per batch row
    reaction_main_kernel<<<B, MAIN_THREADS, SMEM_FLOATS * sizeof(float)>>>(
        y_in, rates_1st, rates_2nd, y_out);
}

// round 3
// speedup vs baseline: 1.3775x; 1.3775x over previous
#include <cuda_runtime.h>
#include <stdint.h>

// Problem constants
#define B     1024
#define S     2048
#define R1    20000
#define R2    40000

#define MAIN_THREADS 512
#define EPT1  40                  // ceil(20000/512) -> padded 20480
#define EPT2  80                  // ceil(40000/512) -> padded 40960
#define PAD1  (EPT1 * MAIN_THREADS)
#define PAD2  (EPT2 * MAIN_THREADS)
#define KPAD  2048u               // dummy key -> scratch accumulator slot

// ---------------- static device scratch (no runtime allocation) ----------------
__device__ int       g_counts1[S];
__device__ int       g_counts2[S];
__device__ int       g_cur1[S];
__device__ int       g_cur2[S];
// Transposed, key-grouped entry streams.
//   e1 = ra | k<<11 | rid<<23          (11 + 12 + 15 bits)
//   e2 = ra | rb<<11 | k<<22 | rid<<34 (11 + 11 + 12 + 16 bits)
__device__ uint64_t  g_e1t[PAD1];
__device__ uint64_t  g_e2t[PAD2];

__device__ __forceinline__ int transpose1(int p) { return (p % EPT1) * MAIN_THREADS + p / EPT1; }
__device__ __forceinline__ int transpose2(int p) { return (p % EPT2) * MAIN_THREADS + p / EPT2; }

// ---------------- prep kernels ----------------

__global__ void init_counts_kernel() {
    int i = blockIdx.x * blockDim.x + threadIdx.x;
    if (i < S) { g_counts1[i] = 0; g_counts2[i] = 0; }
}

__global__ void hist_kernel(const int* __restrict__ inds_1p,
                            const int* __restrict__ inds_2p) {
    int i = blockIdx.x * blockDim.x + threadIdx.x;
    if (i < R1) {
        atomicAdd(&g_counts1[inds_1p[i]], 1);
    } else if (i < R1 + R2) {
        atomicAdd(&g_counts2[inds_2p[i - R1]], 1);
    }
}

// Single-CTA exclusive scan over 2048 bins (twice), writing running cursors.
__global__ void scan_kernel() {
    __shared__ int buf[2][S];
    const int tid = threadIdx.x;   // 1024 threads, 2 elems each

    for (int pass = 0; pass < 2; ++pass) {
        const int* cnt = pass == 0 ? g_counts1 : g_counts2;
        int*       cur = pass == 0 ? g_cur1    : g_cur2;

        buf[0][tid]        = cnt[tid];
        buf[0][tid + 1024] = cnt[tid + 1024];
        __syncthreads();

        int src = 0;
        for (int off = 1; off < S; off <<= 1) {
            int i0 = tid, i1 = tid + 1024;
            int v0 = buf[src][i0] + (i0 >= off ? buf[src][i0 - off] : 0);
            int v1 = buf[src][i1] + (i1 >= off ? buf[src][i1 - off] : 0);
            __syncthreads();
            buf[1 - src][i0] = v0;
            buf[1 - src][i1] = v1;
            __syncthreads();
            src ^= 1;
        }
        cur[tid]        = (tid == 0) ? 0 : buf[src][tid - 1];
        cur[tid + 1024] = buf[src][tid + 1023];
        __syncthreads();
    }
}

__global__ void scatter_kernel(const int* __restrict__ inds_1r,
                               const int* __restrict__ inds_1p,
                               const int* __restrict__ inds_2r,
                               const int* __restrict__ inds_2p) {
    int i = blockIdx.x * blockDim.x + threadIdx.x;
    if (i < R1) {
        int p  = inds_1p[i];
        int pos = atomicAdd(&g_cur1[p], 1);
        g_e1t[transpose1(pos)] =
              (uint64_t)(uint32_t)inds_1r[i]
            | ((uint64_t)(uint32_t)p << 11)
            | ((uint64_t)(uint32_t)i << 23);
    } else if (i < R1 + R2) {
        int j  = i - R1;
        int p  = inds_2p[j];
        int pos = atomicAdd(&g_cur2[p], 1);
        g_e2t[transpose2(pos)] =
              (uint64_t)(uint32_t)inds_2r[2 * j]
            | ((uint64_t)(uint32_t)inds_2r[2 * j + 1] << 11)
            | ((uint64_t)(uint32_t)p                  << 22)
            | ((uint64_t)(uint32_t)j                  << 34);
    }
}

// Fill padding slots (sorted positions >= R) with dummy entries (key = 2048).
__global__ void pad_kernel() {
    int i = blockIdx.x * blockDim.x + threadIdx.x;
    if (i < PAD1 - R1)
        g_e1t[transpose1(R1 + i)] = ((uint64_t)KPAD << 11);
    if (i < PAD2 - R2)
        g_e2t[transpose2(R2 + i)] = ((uint64_t)KPAD << 22);
}

// ---------------- main kernel ----------------
// One CTA per batch row. Each thread owns a fixed contiguous slice of the
// key-sorted entry stream (loaded coalesced via the transposed layout),
// accumulates per-key partial sums in a register, and flushes to the SMEM
// accumulator only on key changes (keys are non-decreasing within a slice).
//
// SMEM: y row (2048) + accumulator (2052, slot 2048 = pad sink) + rates (40000)

#define ACC_FLOATS 2052
#define SMEM_FLOATS (S + ACC_FLOATS + R2)   // 44100 floats = 176,400 B

__global__ __launch_bounds__(MAIN_THREADS, 1)
void reaction_main_kernel(const float* __restrict__ y_in,
                          const float* __restrict__ rates_1st,
                          const float* __restrict__ rates_2nd,
                          float* __restrict__ y_out) {
    extern __shared__ float sm[];
    float* y_s   = sm;                 // [S]
    float* acc_s = sm + S;             // [ACC_FLOATS]
    float* rbuf  = sm + S + ACC_FLOATS;// [R2]

    const int b   = blockIdx.x;
    const int tid = threadIdx.x;

    // Load y row (one float4/thread) and zero the accumulator.
    {
        const float4* src = (const float4*)(y_in + (size_t)b * S);
        ((float4*)y_s)[tid] = src[tid];
        for (int i = tid; i < ACC_FLOATS; i += MAIN_THREADS)
            acc_s[i] = 0.f;
    }

    // ---- Phase A: stage rates_1st (coalesced float4) ----
    {
        const float4* src = (const float4*)(rates_1st + (size_t)b * R1);
        #pragma unroll
        for (int i = tid; i < R1 / 4; i += MAIN_THREADS)
            ((float4*)rbuf)[i] = src[i];
    }
    __syncthreads();

    // ---- Phase A: balanced slice sweep, register accumulation ----
    {
        unsigned curk = 0xFFFFFFFFu;
        float    a    = 0.f;
        #pragma unroll 8
        for (int j = 0; j < EPT1; ++j) {
            uint64_t e  = g_e1t[j * MAIN_THREADS + tid];   // coalesced LDG.64
            unsigned ra  = (unsigned)e & 2047u;
            unsigned k   = ((unsigned)(e >> 11)) & 4095u;
            unsigned rid = (unsigned)(e >> 23);
            float v = y_s[ra] * rbuf[rid];
            if (k != curk) {
                if (curk != 0xFFFFFFFFu) atomicAdd(&acc_s[curk], a);
                curk = k; a = v;
            } else {
                a += v;
            }
        }
        atomicAdd(&acc_s[curk], a);
    }
    __syncthreads();   // all phase-A rbuf reads done before overwrite

    // ---- Phase B: stage rates_2nd ----
    {
        const float4* src = (const float4*)(rates_2nd + (size_t)b * R2);
        #pragma unroll
        for (int i = tid; i < R2 / 4; i += MAIN_THREADS)
            ((float4*)rbuf)[i] = src[i];
    }
    __syncthreads();

    // ---- Phase B: balanced slice sweep ----
    {
        unsigned curk = 0xFFFFFFFFu;
        float    a    = 0.f;
        #pragma unroll 8
        for (int j = 0; j < EPT2; ++j) {
            uint64_t e  = g_e2t[j * MAIN_THREADS + tid];   // coalesced LDG.64
            unsigned ra  = (unsigned)e & 2047u;
            unsigned rb  = ((unsigned)(e >> 11)) & 2047u;
            unsigned k   = ((unsigned)(e >> 22)) & 4095u;
            unsigned rid = (unsigned)(e >> 34);
            float v = y_s[ra] * y_s[rb] * rbuf[rid];
            if (k != curk) {
                if (curk != 0xFFFFFFFFu) atomicAdd(&acc_s[curk], a);
                curk = k; a = v;
            } else {
                a += v;
            }
        }
        atomicAdd(&acc_s[curk], a);
    }
    __syncthreads();

    // ---- write out (coalesced float4, first S slots only) ----
    ((float4*)(y_out + (size_t)b * S))[tid] = ((const float4*)acc_s)[tid];
}

// ---------------- launch ----------------

extern "C" void kernel_launch(void* const* d_in, const int* in_sizes, int n_in,
                              void* d_out, int out_size) {
    const float* y_in      = (const float*)d_in[0];
    const float* rates_1st = (const float*)d_in[1];
    const float* rates_2nd = (const float*)d_in[2];
    const int*   inds_1r   = (const int*)d_in[3];
    const int*   inds_1p   = (const int*)d_in[4];
    const int*   inds_2r   = (const int*)d_in[5];
    const int*   inds_2p   = (const int*)d_in[6];
    float*       y_out     = (float*)d_out;

    cudaFuncSetAttribute(reaction_main_kernel,
                         cudaFuncAttributeMaxDynamicSharedMemorySize,
                         SMEM_FLOATS * (int)sizeof(float));

    // Entry-stream build (rebuilt every launch; deterministic)
    init_counts_kernel<<<(S + 255) / 256, 256>>>();
    hist_kernel<<<(R1 + R2 + 255) / 256, 256>>>(inds_1p, inds_2p);
    scan_kernel<<<1, 1024>>>();
    scatter_kernel<<<(R1 + R2 + 255) / 256, 256>>>(inds_1r, inds_1p, inds_2r, inds_2p);
    pad_kernel<<<(PAD2 - R2 + 255) / 256, 256>>>();

    // Main pass: one CTA per batch row
    reaction_main_kernel<<<B, MAIN_THREADS, SMEM_FLOATS * sizeof(float)>>>(
        y_in, rates_1st, rates_2nd, y_out);
}

// round 4
// speedup vs baseline: 2.0167x; 1.4640x over previous
#include <cuda_runtime.h>
#include <stdint.h>

// Problem constants
#define B     1024
#define S     2048
#define R1    20000
#define R2    40000

#define MAIN_THREADS 512
#define EPT1  40                  // ceil(20000/512) -> padded 20480
#define EPT2  80                  // ceil(40000/512) -> padded 40960
#define PAD1  (EPT1 * MAIN_THREADS)
#define PAD2  (EPT2 * MAIN_THREADS)
#define KPAD  2048u               // dummy key -> scratch accumulator slot
#define CHUNK 8

// ---------------- static device scratch (no runtime allocation) ----------------
__device__ int       g_counts1[S];
__device__ int       g_counts2[S];
__device__ int       g_cur1[S];
__device__ int       g_cur2[S];
// Transposed, key-grouped entry streams.
//   e1 = ra | k<<11 | rid<<23          (11 + 12 + 15 bits)
//   e2 = ra | rb<<11 | k<<22 | rid<<34 (11 + 11 + 12 + 16 bits)
__device__ uint64_t  g_e1t[PAD1];
__device__ uint64_t  g_e2t[PAD2];

__device__ __forceinline__ int transpose1(int p) { return (p % EPT1) * MAIN_THREADS + p / EPT1; }
__device__ __forceinline__ int transpose2(int p) { return (p % EPT2) * MAIN_THREADS + p / EPT2; }

// ---------------- prep kernels ----------------

__global__ void init_counts_kernel() {
    int i = blockIdx.x * blockDim.x + threadIdx.x;
    if (i < S) { g_counts1[i] = 0; g_counts2[i] = 0; }
}

__global__ void hist_kernel(const int* __restrict__ inds_1p,
                            const int* __restrict__ inds_2p) {
    int i = blockIdx.x * blockDim.x + threadIdx.x;
    if (i < R1) {
        atomicAdd(&g_counts1[inds_1p[i]], 1);
    } else if (i < R1 + R2) {
        atomicAdd(&g_counts2[inds_2p[i - R1]], 1);
    }
}

// Single-CTA exclusive scan over 2048 bins (twice), writing running cursors.
__global__ void scan_kernel() {
    __shared__ int buf[2][S];
    const int tid = threadIdx.x;   // 1024 threads, 2 elems each

    for (int pass = 0; pass < 2; ++pass) {
        const int* cnt = pass == 0 ? g_counts1 : g_counts2;
        int*       cur = pass == 0 ? g_cur1    : g_cur2;

        buf[0][tid]        = cnt[tid];
        buf[0][tid + 1024] = cnt[tid + 1024];
        __syncthreads();

        int src = 0;
        for (int off = 1; off < S; off <<= 1) {
            int i0 = tid, i1 = tid + 1024;
            int v0 = buf[src][i0] + (i0 >= off ? buf[src][i0 - off] : 0);
            int v1 = buf[src][i1] + (i1 >= off ? buf[src][i1 - off] : 0);
            __syncthreads();
            buf[1 - src][i0] = v0;
            buf[1 - src][i1] = v1;
            __syncthreads();
            src ^= 1;
        }
        cur[tid]        = (tid == 0) ? 0 : buf[src][tid - 1];
        cur[tid + 1024] = buf[src][tid + 1023];
        __syncthreads();
    }
}

__global__ void scatter_kernel(const int* __restrict__ inds_1r,
                               const int* __restrict__ inds_1p,
                               const int* __restrict__ inds_2r,
                               const int* __restrict__ inds_2p) {
    int i = blockIdx.x * blockDim.x + threadIdx.x;
    if (i < R1) {
        int p  = inds_1p[i];
        int pos = atomicAdd(&g_cur1[p], 1);
        g_e1t[transpose1(pos)] =
              (uint64_t)(uint32_t)inds_1r[i]
            | ((uint64_t)(uint32_t)p << 11)
            | ((uint64_t)(uint32_t)i << 23);
    } else if (i < R1 + R2) {
        int j  = i - R1;
        int p  = inds_2p[j];
        int pos = atomicAdd(&g_cur2[p], 1);
        g_e2t[transpose2(pos)] =
              (uint64_t)(uint32_t)inds_2r[2 * j]
            | ((uint64_t)(uint32_t)inds_2r[2 * j + 1] << 11)
            | ((uint64_t)(uint32_t)p                  << 22)
            | ((uint64_t)(uint32_t)j                  << 34);
    }
}

// Fill padding slots (sorted positions >= R) with dummy entries (key = 2048).
__global__ void pad_kernel() {
    int i = blockIdx.x * blockDim.x + threadIdx.x;
    if (i < PAD1 - R1)
        g_e1t[transpose1(R1 + i)] = ((uint64_t)KPAD << 11);
    if (i < PAD2 - R2)
        g_e2t[transpose2(R2 + i)] = ((uint64_t)KPAD << 22);
}

// ---------------- main kernel ----------------
// One CTA per batch row. Each thread owns a fixed contiguous slice of the
// key-sorted entry stream (coalesced via transposed layout). Entries are
// loaded in branch-free register chunks with double buffering (MLP=8),
// then processed with register accumulation + SMEM-atomic flush on key change.
//
// SMEM: y row (2048) + accumulator (2052, slot 2048 = pad sink) + rates (40000)

#define ACC_FLOATS 2052
#define SMEM_FLOATS (S + ACC_FLOATS + R2)   // 44100 floats = 176,400 B

__global__ __launch_bounds__(MAIN_THREADS, 1)
void reaction_main_kernel(const float* __restrict__ y_in,
                          const float* __restrict__ rates_1st,
                          const float* __restrict__ rates_2nd,
                          float* __restrict__ y_out) {
    extern __shared__ float sm[];
    float* y_s   = sm;                 // [S]
    float* acc_s = sm + S;             // [ACC_FLOATS]
    float* rbuf  = sm + S + ACC_FLOATS;// [R2]

    const int b   = blockIdx.x;
    const int tid = threadIdx.x;

    // Load y row (one float4/thread) and zero the accumulator.
    {
        const float4* src = (const float4*)(y_in + (size_t)b * S);
        ((float4*)y_s)[tid] = src[tid];
        for (int i = tid; i < ACC_FLOATS; i += MAIN_THREADS)
            acc_s[i] = 0.f;
    }

    // ---- Phase A: stage rates_1st (coalesced float4, streaming hint) ----
    {
        const float4* src = (const float4*)(rates_1st + (size_t)b * R1);
        #pragma unroll
        for (int i = tid; i < R1 / 4; i += MAIN_THREADS)
            ((float4*)rbuf)[i] = __ldcs(src + i);
    }
    __syncthreads();

    // ---- Phase A: chunked sweep, double-buffered loads, register accum ----
    {
        const uint64_t* __restrict__ ep = g_e1t + tid;
        uint64_t buf0[CHUNK], buf1[CHUNK];
        unsigned curk = KPAD;           // sink slot; always flushable
        float    a    = 0.f;

        #pragma unroll
        for (int u = 0; u < CHUNK; ++u)
            buf0[u] = ep[u * MAIN_THREADS];

        #pragma unroll
        for (int c = 0; c < EPT1 / CHUNK; ++c) {
            uint64_t* cur = (c & 1) ? buf1 : buf0;
            uint64_t* nxt = (c & 1) ? buf0 : buf1;
            if (c + 1 < EPT1 / CHUNK) {
                const uint64_t* np = ep + (c + 1) * CHUNK * MAIN_THREADS;
                #pragma unroll
                for (int u = 0; u < CHUNK; ++u)
                    nxt[u] = np[u * MAIN_THREADS];
            }
            #pragma unroll
            for (int u = 0; u < CHUNK; ++u) {
                uint64_t e   = cur[u];
                unsigned ra  = (unsigned)e & 2047u;
                unsigned k   = ((unsigned)(e >> 11)) & 4095u;
                unsigned rid = (unsigned)(e >> 23);
                float v = y_s[ra] * rbuf[rid];
                if (k != curk) {
                    atomicAdd(&acc_s[curk], a);
                    curk = k; a = v;
                } else {
                    a += v;
                }
            }
        }
        atomicAdd(&acc_s[curk], a);
    }
    __syncthreads();   // all phase-A rbuf reads done before overwrite

    // ---- Phase B: stage rates_2nd ----
    {
        const float4* src = (const float4*)(rates_2nd + (size_t)b * R2);
        #pragma unroll
        for (int i = tid; i < R2 / 4; i += MAIN_THREADS)
            ((float4*)rbuf)[i] = __ldcs(src + i);
    }
    __syncthreads();

    // ---- Phase B: chunked sweep ----
    {
        const uint64_t* __restrict__ ep = g_e2t + tid;
        uint64_t buf0[CHUNK], buf1[CHUNK];
        unsigned curk = KPAD;
        float    a    = 0.f;

        #pragma unroll
        for (int u = 0; u < CHUNK; ++u)
            buf0[u] = ep[u * MAIN_THREADS];

        #pragma unroll
        for (int c = 0; c < EPT2 / CHUNK; ++c) {
            uint64_t* cur = (c & 1) ? buf1 : buf0;
            uint64_t* nxt = (c & 1) ? buf0 : buf1;
            if (c + 1 < EPT2 / CHUNK) {
                const uint64_t* np = ep + (c + 1) * CHUNK * MAIN_THREADS;
                #pragma unroll
                for (int u = 0; u < CHUNK; ++u)
                    nxt[u] = np[u * MAIN_THREADS];
            }
            #pragma unroll
            for (int u = 0; u < CHUNK; ++u) {
                uint64_t e   = cur[u];
                unsigned ra  = (unsigned)e & 2047u;
                unsigned rb  = ((unsigned)(e >> 11)) & 2047u;
                unsigned k   = ((unsigned)(e >> 22)) & 4095u;
                unsigned rid = (unsigned)(e >> 34);
                float v = y_s[ra] * y_s[rb] * rbuf[rid];
                if (k != curk) {
                    atomicAdd(&acc_s[curk], a);
                    curk = k; a = v;
                } else {
                    a += v;
                }
            }
        }
        atomicAdd(&acc_s[curk], a);
    }
    __syncthreads();

    // ---- write out (coalesced float4, first S slots only) ----
    ((float4*)(y_out + (size_t)b * S))[tid] = ((const float4*)acc_s)[tid];
}

// ---------------- launch ----------------

extern "C" void kernel_launch(void* const* d_in, const int* in_sizes, int n_in,
                              void* d_out, int out_size) {
    const float* y_in      = (const float*)d_in[0];
    const float* rates_1st = (const float*)d_in[1];
    const float* rates_2nd = (const float*)d_in[2];
    const int*   inds_1r   = (const int*)d_in[3];
    const int*   inds_1p   = (const int*)d_in[4];
    const int*   inds_2r   = (const int*)d_in[5];
    const int*   inds_2p   = (const int*)d_in[6];
    float*       y_out     = (float*)d_out;

    cudaFuncSetAttribute(reaction_main_kernel,
                         cudaFuncAttributeMaxDynamicSharedMemorySize,
                         SMEM_FLOATS * (int)sizeof(float));

    // Entry-stream build (rebuilt every launch; deterministic)
    init_counts_kernel<<<(S + 255) / 256, 256>>>();
    hist_kernel<<<(R1 + R2 + 255) / 256, 256>>>(inds_1p, inds_2p);
    scan_kernel<<<1, 1024>>>();
    scatter_kernel<<<(R1 + R2 + 255) / 256, 256>>>(inds_1r, inds_1p, inds_2r, inds_2p);
    pad_kernel<<<(PAD2 - R2 + 255) / 256, 256>>>();

    // Main pass: one CTA per batch row
    reaction_main_kernel<<<B, MAIN_THREADS, SMEM_FLOATS * sizeof(float)>>>(
        y_in, rates_1st, rates_2nd, y_out);
}